// round 8
// baseline (speedup 1.0000x reference)
#include <cuda_runtime.h>
#include <cuda_bf16.h>
#include <math.h>
#include <stdint.h>

#define Bz 32
#define Sz 512
#define NB 20
#define EMB 128
#define INNER 128
#define VOCAB 40000
#define QL 20
#define NGRP (Bz * Sz)
#define NTILES 2731            // ceil(16384 / 6)

typedef unsigned long long u64;
typedef unsigned int u32;

// ---- packed f32x2 helpers ----
__device__ __forceinline__ u64 dup2(float a) {
    u64 r; asm("mov.b64 %0, {%1, %1};" : "=l"(r) : "f"(a)); return r;
}
__device__ __forceinline__ u64 pack2(float x, float y) {
    u64 r; asm("mov.b64 %0, {%1, %2};" : "=l"(r) : "f"(x), "f"(y)); return r;
}
__device__ __forceinline__ float2 unpack2(u64 v) {
    float2 f; asm("mov.b64 {%0, %1}, %2;" : "=f"(f.x), "=f"(f.y) : "l"(v)); return f;
}
__device__ __forceinline__ void ffma2(u64& d, u64 a, u64 b) {
    asm("fma.rn.f32x2 %0, %1, %2, %0;" : "+l"(d) : "l"(a), "l"(b));
}
__device__ __forceinline__ float neg_inf_f() { return __int_as_float(0xff800000); }
__device__ __forceinline__ float tanh_fast(float x) {
    float e = __expf(2.f * x);
    return 1.f - __fdividef(2.f, e + 1.f);
}

// ---- scratch ----
__device__ float g_qc[Bz * INNER];
__device__ float g_tfv[Bz * INNER];
__device__ float g_uH[Bz * EMB];
__device__ float g_kb[NB * INNER];
__device__ u64   g_DE[EMB * INNER];
__device__ float g_tm[Bz * Sz * EMB];
__device__ float g_talign[Bz * Sz];
__device__ float g_ob[Bz * EMB];
__device__ unsigned char g_ATsw[69632];   // A^T bf16 hi/lo images, 272B row stride

// ---- warp mma helpers ----
__device__ __forceinline__ u32 smem_u32(const void* p) {
    u32 a; asm("{ .reg .u64 t; cvta.to.shared.u64 t, %1; cvt.u32.u64 %0, t; }" : "=r"(a) : "l"(p));
    return a;
}
__device__ __forceinline__ void ldsm4(u32* r, u32 addr) {
    asm volatile("ldmatrix.sync.aligned.m8n8.x4.shared.b16 {%0,%1,%2,%3}, [%4];"
        : "=r"(r[0]), "=r"(r[1]), "=r"(r[2]), "=r"(r[3]) : "r"(addr));
}
__device__ __forceinline__ void mma16816(float* d, const u32* a, u32 b0, u32 b1) {
    asm volatile("mma.sync.aligned.m16n8k16.row.col.f32.bf16.bf16.f32 "
        "{%0,%1,%2,%3}, {%4,%5,%6,%7}, {%8,%9}, {%0,%1,%2,%3};"
        : "+f"(d[0]), "+f"(d[1]), "+f"(d[2]), "+f"(d[3])
        : "r"(a[0]), "r"(a[1]), "r"(a[2]), "r"(a[3]), "r"(b0), "r"(b1));
}

#define BAR_SYNC(id, n)   asm volatile("bar.sync %0, %1;"   :: "r"(id), "r"(n) : "memory")
#define BAR_ARRIVE(id, n) asm volatile("bar.arrive %0, %1;" :: "r"(id), "r"(n) : "memory")

// smem layout (bytes)
#define IMG    34816
#define BUFSZ  69632
#define AT_OFF 139264
#define KB_OFF 208896
#define SV_OFF 220480
#define ALN_OFF 220992          // double-buffered: 2 x 128 floats
#define SPB_OFF 222016          // producer-private spb [128]
#define DYN_SMEM 222528

// ============================================================
// k_setup: prep(32) | kb(20)
// ============================================================
__global__ void __launch_bounds__(128) k_setup(
    const int* __restrict__ queries, const int* __restrict__ keys,
    const float* __restrict__ emb, const float* __restrict__ mmask,
    const float* __restrict__ C, const float* __restrict__ F,
    const float* __restrict__ H, const float* __restrict__ Bm)
{
    const int blk = blockIdx.x, tid = threadIdx.x;
    if (blk < 32) {
        const int b = blk;
        __shared__ float su[EMB];
        float u = 0.f;
#pragma unroll
        for (int q = 0; q < QL; q++)
            u += emb[(size_t)queries[b * QL + q] * EMB + tid] * mmask[q * EMB + tid];
        su[tid] = u;
        __syncthreads();
        float c = 0.f, f = 0.f, h = 0.f;
#pragma unroll 4
        for (int e = 0; e < EMB; e++) {
            const float ue = su[e];
            c += ue * C[e * INNER + tid];
            f += ue * F[e * INNER + tid];
            h += ue * H[e * EMB + tid];
        }
        g_qc[b * INNER + tid]  = c;
        g_tfv[b * INNER + tid] = f;
        g_uH[b * EMB + tid]    = h;
    } else {
        const int n = blk - 32;
        __shared__ float se[EMB];
        se[tid] = emb[(size_t)keys[n] * EMB + tid];
        __syncthreads();
        float a = 0.f;
#pragma unroll 4
        for (int e = 0; e < EMB; e++) a += se[e] * Bm[e * INNER + tid];
        g_kb[n * INNER + tid] = a;
    }
}

__global__ void __launch_bounds__(128) k_de(const float* __restrict__ D,
                                            const float* __restrict__ E)
{
    const int i = blockIdx.x * 128 + threadIdx.x;
    g_DE[i] = pack2(D[i], E[i]);
}

__global__ void __launch_bounds__(128) k_splitA(const float* __restrict__ A)
{
    const int idx = blockIdx.x * 128 + threadIdx.x;
    const int e = idx >> 7, i = idx & 127;
    const float x = A[e * 128 + i];
    const __nv_bfloat16 h = __float2bfloat16_rn(x);
    const __nv_bfloat16 l = __float2bfloat16_rn(x - __bfloat162float(h));
    *(unsigned short*)(g_ATsw + i * 272 + e * 2)       = __bfloat16_as_ushort(h);
    *(unsigned short*)(g_ATsw + IMG + i * 272 + e * 2) = __bfloat16_as_ushort(l);
}

// ============================================================
// k_hmma: persistent; producers = load + softmax + tm; consumers = MMA + tanh
// ============================================================
__device__ __forceinline__ void cvt_store(char* bufp, int r, int c16, float4 x)
{
    const __nv_bfloat16 h0 = __float2bfloat16_rn(x.x);
    const __nv_bfloat16 h1 = __float2bfloat16_rn(x.y);
    const __nv_bfloat16 h2 = __float2bfloat16_rn(x.z);
    const __nv_bfloat16 h3 = __float2bfloat16_rn(x.w);
    const __nv_bfloat16 l0 = __float2bfloat16_rn(x.x - __bfloat162float(h0));
    const __nv_bfloat16 l1 = __float2bfloat16_rn(x.y - __bfloat162float(h1));
    const __nv_bfloat16 l2 = __float2bfloat16_rn(x.z - __bfloat162float(h2));
    const __nv_bfloat16 l3 = __float2bfloat16_rn(x.w - __bfloat162float(h3));
    uint2 hp, lp;
    hp.x = (u32)__bfloat16_as_ushort(h0) | ((u32)__bfloat16_as_ushort(h1) << 16);
    hp.y = (u32)__bfloat16_as_ushort(h2) | ((u32)__bfloat16_as_ushort(h3) << 16);
    lp.x = (u32)__bfloat16_as_ushort(l0) | ((u32)__bfloat16_as_ushort(l1) << 16);
    lp.y = (u32)__bfloat16_as_ushort(l2) | ((u32)__bfloat16_as_ushort(l3) << 16);
    *(uint2*)(bufp + r * 272 + c16 * 8)       = hp;
    *(uint2*)(bufp + IMG + r * 272 + c16 * 8) = lp;
}

__device__ __forceinline__ void load_tile(char* sm, const float* __restrict__ mem,
                                          int Gt0, int ng, int buf, int ptid)
{
    char* bufp = sm + buf * BUFSZ;
    const float* src = mem + (size_t)Gt0 * (NB * EMB);
    if (ng == 6) {
#pragma unroll
        for (int c = 0; c < 5; c++) {
            float4 x[6];
#pragma unroll
            for (int j = 0; j < 6; j++) {
                const int idx = ptid + (c * 6 + j) * 128;
                x[j] = *((const float4*)(src + (size_t)(idx >> 5) * 128) + (idx & 31));
            }
#pragma unroll
            for (int j = 0; j < 6; j++) {
                const int idx = ptid + (c * 6 + j) * 128;
                cvt_store(bufp, idx >> 5, idx & 31, x[j]);
            }
        }
    } else {
        const int iters = ng * 20 * 32;
        for (int idx = ptid; idx < iters; idx += 128) {
            const float4 x = *((const float4*)(src + (size_t)(idx >> 5) * 128) + (idx & 31));
            cvt_store(bufp, idx >> 5, idx & 31, x);
        }
    }
}

__global__ void __launch_bounds__(384, 1) k_hmma(const float* __restrict__ mem,
                                                 const float* __restrict__ v)
{
    extern __shared__ char sm[];
    const int tid = threadIdx.x, w = tid >> 5, lane = tid & 31;
    const u32 smb = smem_u32(sm);

    {
        const uint4* src = (const uint4*)g_ATsw;
        uint4* dst = (uint4*)(sm + AT_OFF);
        for (int k = tid; k < BUFSZ / 16; k += 384) dst[k] = src[k];
    }
    for (int idx = tid; idx < 20 * 128; idx += 384) {
        const int n = idx >> 7, e = idx & 127;
        ((float*)(sm + KB_OFF))[n * 132 + e] = g_kb[n * 128 + e];
    }
    if (tid < 128) ((float*)(sm + SV_OFF))[tid] = v[tid];
    __syncthreads();

    float* aln = (float*)(sm + ALN_OFF);
    float* spb = (float*)(sm + SPB_OFF);

    if (w >= 8) {
        // ---------------- producers: load + softmax + tm ----------------
        const int ptid = tid - 256;
        // prologue: load tile 0 into buf 0
        {
            const int tt0 = blockIdx.x;
            load_tile(sm, mem, tt0 * 6, min(6, NGRP - tt0 * 6), 0, ptid);
            BAR_ARRIVE(1, 384);               // full buf0
        }
        int lt = 0;
        for (int tt = blockIdx.x; tt < NTILES; tt += gridDim.x, lt++) {
            const int ttn = tt + gridDim.x;
            if (ttn < NTILES) {
                if (lt >= 1) BAR_SYNC(3 + ((lt + 1) & 1), 384);   // buf free
                load_tile(sm, mem, ttn * 6, min(6, NGRP - ttn * 6), (lt + 1) & 1, ptid);
                BAR_ARRIVE(1 + ((lt + 1) & 1), 384);              // buf full
            }
            BAR_SYNC(5 + (lt & 1), 384);      // aln(lt) ready
            // ---- epilogue for tile tt: softmax + tm ----
            const int Gt0 = tt * 6;
            const int ng = min(6, NGRP - Gt0);
            const int rows = ng * 20;
            const float* alnP = aln + (lt & 1) * 128;
            float myspb = 0.f;
            if (ptid < rows) {
                const int gb = (ptid / 20) * 20;
                float mx = -1e30f;
#pragma unroll
                for (int n2 = 0; n2 < 20; n2++) mx = fmaxf(mx, alnP[gb + n2]);
                float Z = 0.f;
#pragma unroll
                for (int n2 = 0; n2 < 20; n2++) Z += __expf(alnP[gb + n2] - mx);
                myspb = __expf(alnP[ptid] - mx) / Z;
            }
            spb[ptid] = myspb;
            BAR_SYNC(9, 128);                 // producer-internal
            BAR_ARRIVE(7 + (lt & 1), 384);    // aln(lt) free (consumers may rewrite)
            {   // tm from exact fp32 global (L1/L2-resident)
                const float* msrc = mem + (size_t)Gt0 * (NB * EMB);
                const int e = ptid;
#pragma unroll 2
                for (int g = 0; g < 6; g++) {
                    if (g < ng) {
                        float accv = 0.f;
                        const int r0 = g * 20;
#pragma unroll
                        for (int n2 = 0; n2 < 20; n2++)
                            accv += spb[r0 + n2] * msrc[(size_t)(r0 + n2) * 128 + e];
                        g_tm[(size_t)(Gt0 + g) * 128 + e] = accv;
                    }
                }
            }
        }
        return;
    }

    // ---------------- consumers: MMA + tanh/rowsum ----------------
    const float* kbs = (const float*)(sm + KB_OFF);
    const float* sv  = (const float*)(sm + SV_OFF);

    const u32 arow = (lane & 7) + ((lane >> 3) & 1) * 8;
    const u32 acol = (lane >> 4) * 16;
    const u32 brow = (lane & 7) + ((lane >> 4) & 1) * 8;
    const u32 bcol = ((lane >> 3) & 1) * 16;
    const u32 abase0 = smb + (w * 16 + arow) * 272 + acol;
    const u32 bbase  = smb + AT_OFF + brow * 272 + bcol;

    int lt = 0;
    for (int tt = blockIdx.x; tt < NTILES; tt += gridDim.x, lt++) {
        BAR_SYNC(1 + (lt & 1), 384);          // buf full

        float acc[16][4];
#pragma unroll
        for (int nt = 0; nt < 16; nt++) { acc[nt][0] = acc[nt][1] = acc[nt][2] = acc[nt][3] = 0.f; }
        const u32 abase = abase0 + (lt & 1) * BUFSZ;
#pragma unroll
        for (int k = 0; k < 8; k++) {
            u32 ahi[4], alo[4], bhi[8][4];
            const u32 aaddr = abase + k * 32;
            ldsm4(ahi, aaddr);
            ldsm4(alo, aaddr + IMG);
#pragma unroll
            for (int p = 0; p < 8; p++) {
                ldsm4(bhi[p], bbase + p * (16 * 272) + k * 32);
                mma16816(acc[2 * p],     ahi, bhi[p][0], bhi[p][1]);
                mma16816(acc[2 * p + 1], ahi, bhi[p][2], bhi[p][3]);
            }
#pragma unroll
            for (int p = 0; p < 8; p++) {
                mma16816(acc[2 * p],     alo, bhi[p][0], bhi[p][1]);
                mma16816(acc[2 * p + 1], alo, bhi[p][2], bhi[p][3]);
            }
#pragma unroll
            for (int p = 0; p < 8; p++) {
                u32 blo[4];
                ldsm4(blo, bbase + p * (16 * 272) + k * 32 + IMG);
                mma16816(acc[2 * p],     ahi, blo[0], blo[1]);
                mma16816(acc[2 * p + 1], ahi, blo[2], blo[3]);
            }
        }
        BAR_ARRIVE(3 + (lt & 1), 384);        // buf free

        // ---- tanh + v-weighted row sums ----
        const int Gt0 = tt * 6;
        const int ng = min(6, NGRP - Gt0);
        const int rA = (w << 4) + (lane >> 2);
        const int rB = rA + 8;
        const int gA = min(rA / 20, ng - 1), gB = min(rB / 20, ng - 1);
        const int nA = rA % 20, nB2 = rB % 20;
        const float* qA = g_qc + (size_t)((Gt0 + gA) >> 9) * 128;
        const float* qB = g_qc + (size_t)((Gt0 + gB) >> 9) * 128;
        const float* kA = kbs + nA * 132;
        const float* kB = kbs + nB2 * 132;
        const int cb = 2 * (lane & 3);
        float sumA = 0.f, sumB = 0.f;
#pragma unroll
        for (int nt = 0; nt < 16; nt++) {
            const int c0 = nt * 8 + cb;
            const float2 ka  = *(const float2*)(kA + c0);
            const float2 kb2 = *(const float2*)(kB + c0);
            const float2 qa  = *(const float2*)(qA + c0);
            const float2 qb  = *(const float2*)(qB + c0);
            const float2 vv  = *(const float2*)(sv + c0);
            sumA += vv.x * tanh_fast(acc[nt][0] + ka.x + qa.x);
            sumA += vv.y * tanh_fast(acc[nt][1] + ka.y + qa.y);
            sumB += vv.x * tanh_fast(acc[nt][2] + kb2.x + qb.x);
            sumB += vv.y * tanh_fast(acc[nt][3] + kb2.y + qb.y);
        }
        sumA += __shfl_xor_sync(0xffffffffu, sumA, 1);
        sumA += __shfl_xor_sync(0xffffffffu, sumA, 2);
        sumB += __shfl_xor_sync(0xffffffffu, sumB, 1);
        sumB += __shfl_xor_sync(0xffffffffu, sumB, 2);

        if (lt >= 2) BAR_SYNC(7 + (lt & 1), 384);   // aln buffer free again
        float* alnP = aln + (lt & 1) * 128;
        if ((lane & 3) == 0) { alnP[rA] = sumA; alnP[rB] = sumB; }
        BAR_ARRIVE(5 + (lt & 1), 384);              // aln ready
    }
}

// ============================================================
#define ST 16
__global__ void __launch_bounds__(128) k_align2(
    const float* __restrict__ stories, const float* __restrict__ w)
{
    const int b = blockIdx.y, s0 = blockIdx.x * ST;
    const int tid = threadIdx.x, lane = tid & 31, wid = tid >> 5;
    __shared__ u64 sp[EMB * ST];
    __shared__ float s_part[4 * ST];
#pragma unroll
    for (int si = 0; si < ST; si++) {
        const size_t base = ((size_t)(b * Sz + s0 + si)) * EMB + tid;
        sp[tid * ST + si] = pack2(g_tm[base], stories[base]);
    }
    __syncthreads();
    u64 acc[ST];
#pragma unroll
    for (int si = 0; si < ST; si++) acc[si] = 0ull;
#pragma unroll 2
    for (int e = 0; e < EMB; e++) {
        const u64 de = g_DE[e * INNER + tid];
        const ulonglong2* row = (const ulonglong2*)(sp + e * ST);
#pragma unroll
        for (int k = 0; k < ST / 2; k++) {
            const ulonglong2 m = row[k];
            ffma2(acc[2 * k],     m.x, de);
            ffma2(acc[2 * k + 1], m.y, de);
        }
    }
    const float tfi = g_tfv[b * INNER + tid];
    const float wi  = w[tid];
    float tv[ST];
#pragma unroll
    for (int si = 0; si < ST; si++) {
        const float2 f = unpack2(acc[si]);
        float t = wi * tanh_fast(f.x + f.y + tfi);
#pragma unroll
        for (int o = 16; o > 0; o >>= 1) t += __shfl_xor_sync(0xffffffffu, t, o);
        tv[si] = t;
    }
    if (lane == 0) {
#pragma unroll
        for (int si = 0; si < ST; si++) s_part[wid * ST + si] = tv[si];
    }
    __syncthreads();
    if (tid < ST)
        g_talign[b * Sz + s0 + tid] =
            s_part[tid] + s_part[ST + tid] + s_part[2 * ST + tid] + s_part[3 * ST + tid];
}

// ============================================================
__global__ void __launch_bounds__(128) k_temporal(const float* __restrict__ mask)
{
    const int ec = blockIdx.x, b = blockIdx.y;
    const int tid = threadIdx.x, lane = tid & 31, wid = tid >> 5;
    __shared__ float sp[Sz];
    __shared__ float sr[4];
    __shared__ float s_part[8][16];

    float vals[4];
    float mx = neg_inf_f();
#pragma unroll
    for (int r = 0; r < 4; r++) {
        const int s = r * 128 + tid;
        const float ta = g_talign[b * Sz + s];
        const float m  = mask[b * Sz + s];
        const float ml = (m != 0.f) ? ta * m : neg_inf_f();
        vals[r] = ml;
        mx = fmaxf(mx, ml);
    }
#pragma unroll
    for (int o = 16; o > 0; o >>= 1) mx = fmaxf(mx, __shfl_xor_sync(0xffffffffu, mx, o));
    if (lane == 0) sr[wid] = mx;
    __syncthreads();
    mx = fmaxf(fmaxf(sr[0], sr[1]), fmaxf(sr[2], sr[3]));
    __syncthreads();
    float Z = 0.f;
#pragma unroll
    for (int r = 0; r < 4; r++) {
        const float ev = __expf(vals[r] - mx);
        sp[r * 128 + tid] = ev;
        Z += ev;
    }
#pragma unroll
    for (int o = 16; o > 0; o >>= 1) Z += __shfl_xor_sync(0xffffffffu, Z, o);
    if (lane == 0) sr[wid] = Z;
    __syncthreads();
    Z = sr[0] + sr[1] + sr[2] + sr[3];
    const float invZ = 1.f / Z;

    const int eo = tid & 15, sl = tid >> 4;
    const int e = ec * 16 + eo;
    const float* tmb = g_tm + (size_t)b * Sz * EMB + e;
    float o_ = 0.f;
#pragma unroll 8
    for (int s2 = 0; s2 < 64; s2++) {
        const int s = sl * 64 + s2;
        o_ += sp[s] * tmb[(size_t)s * EMB];
    }
    s_part[sl][eo] = o_;
    __syncthreads();
    if (tid < 16) {
        float t = 0.f;
#pragma unroll
        for (int k = 0; k < 8; k++) t += s_part[k][tid];
        const int eg = ec * 16 + tid;
        g_ob[b * EMB + eg] = t * invZ + g_uH[b * EMB + eg];
    }
}

__global__ void __launch_bounds__(128) k_logits(const float* __restrict__ R,
                                                float* __restrict__ out)
{
    __shared__ u64 so2[EMB * (Bz / 2)];
    const int tid = threadIdx.x;
#pragma unroll
    for (int r = 0; r < EMB * (Bz / 2) / 128; r++) {
        const int idx = r * 128 + tid;
        const int e = idx >> 4, bb = idx & 15;
        so2[idx] = pack2(g_ob[(2 * bb) * EMB + e], g_ob[(2 * bb + 1) * EMB + e]);
    }
    __syncthreads();
    const int col = blockIdx.x * 128 + tid;
    if (col >= VOCAB) return;
    u64 acc[Bz / 2];
#pragma unroll
    for (int j = 0; j < Bz / 2; j++) acc[j] = 0ull;
#pragma unroll 8
    for (int e = 0; e < EMB; e++) {
        const u64 rd = dup2(R[(size_t)e * VOCAB + col]);
        const u64* row = so2 + e * (Bz / 2);
#pragma unroll
        for (int bb = 0; bb < Bz / 2; bb++) ffma2(acc[bb], rd, row[bb]);
    }
#pragma unroll
    for (int bb = 0; bb < Bz / 2; bb++) {
        const float2 f = unpack2(acc[bb]);
        out[(size_t)(2 * bb) * VOCAB + col]     = f.x;
        out[(size_t)(2 * bb + 1) * VOCAB + col] = f.y;
    }
}

// ============================================================
extern "C" void kernel_launch(void* const* d_in, const int* in_sizes, int n_in,
                              void* d_out, int out_size)
{
    const float* memories = (const float*)d_in[0];
    const float* stories  = (const float*)d_in[1];
    const float* smask    = (const float*)d_in[2];
    const int*   queries  = (const int*)  d_in[3];
    const int*   keys     = (const int*)  d_in[4];
    const float* emb      = (const float*)d_in[5];
    const float* mmask    = (const float*)d_in[6];
    const float* A        = (const float*)d_in[7];
    const float* Bm       = (const float*)d_in[8];
    const float* C        = (const float*)d_in[9];
    const float* v        = (const float*)d_in[10];
    const float* D        = (const float*)d_in[11];
    const float* E        = (const float*)d_in[12];
    const float* F        = (const float*)d_in[13];
    const float* w        = (const float*)d_in[14];
    const float* H        = (const float*)d_in[15];
    const float* R        = (const float*)d_in[16];
    float* out = (float*)d_out;

    cudaFuncSetAttribute(k_hmma, cudaFuncAttributeMaxDynamicSharedMemorySize, DYN_SMEM);

    // k_hmma kept at launch index 3 (the slot ncu captures)
    k_setup<<<52, 128>>>(queries, keys, emb, mmask, C, F, H, Bm);
    k_de<<<EMB * INNER / 128, 128>>>(D, E);
    k_splitA<<<EMB * INNER / 128, 128>>>(A);
    k_hmma<<<148, 384, DYN_SMEM>>>(memories, v);
    k_align2<<<dim3(Sz / ST, Bz), 128>>>(stories, w);
    k_temporal<<<dim3(8, Bz), 128>>>(smask);
    k_logits<<<(VOCAB + 127) / 128, 128>>>(R, out);
}